// round 4
// baseline (speedup 1.0000x reference)
#include <cuda_runtime.h>

#define K_CTX 64
#define D     128
#define DS    200
#define STRIDE  130   // padded smem row stride (words) -> conflict-free pattern
#define SSTRIDE 65

// AM = table[t1_ctx] @ att_mat, computed once per launch by prep_kernel
__device__ float g_AM[K_CTX * D];

__global__ void prep_kernel(const float* __restrict__ table,
                            const float* __restrict__ att,
                            const int* __restrict__ t1_ctx) {
    __shared__ float sA[D];
    const int k = blockIdx.x;
    const int j = threadIdx.x;
    size_t idx = (size_t)t1_ctx[k];
    sA[j] = table[idx * D + j];
    __syncthreads();
    float acc = 0.f;
#pragma unroll 8
    for (int d = 0; d < D; ++d)
        acc = fmaf(sA[d], att[d * D + j], acc);
    g_AM[k * D + j] = acc;
}

__global__ __launch_bounds__(256, 2)
void main_kernel(const float* __restrict__ table,
                 const float* __restrict__ str_t1,
                 const float* __restrict__ str_t2s,
                 const float* __restrict__ W,
                 const float* __restrict__ b_bi,
                 const int* __restrict__ t1_ctx,
                 const int* __restrict__ t2_ctx,
                 float* __restrict__ out) {
    extern __shared__ float sm[];
    float* sAM = sm;                          // 64*130
    float* sB  = sAM + K_CTX * STRIDE;        // 64*130
    float* sS  = sB  + K_CTX * STRIDE;        // 64*65
    float* red = sS  + K_CTX * SSTRIDE;       // 256
    float* rw  = red + 256;                   // 64 row weights
    float* cw  = rw  + 64;                    // 64 col weights
    float* nA  = cw  + 64;                    // 128
    float* nB  = nA  + 128;                   // 128
    float* sc  = nB  + 128;                   // 4 scalars

    __shared__ int sIdx[K_CTX];

    const int t = threadIdx.x;
    const int c = blockIdx.x;

    // ---- stage smem: AM (from prep), t1 indices, gather B rows ----
    if (t < K_CTX) sIdx[t] = t1_ctx[t];

    for (int i = t; i < K_CTX * D; i += 256)
        sAM[(i >> 7) * STRIDE + (i & 127)] = g_AM[i];

    {
        const int r = t >> 2;       // row 0..63 (4 threads per row)
        const int l = t & 3;
        size_t idx = (size_t)t2_ctx[c * K_CTX + r];
        const float2* src = (const float2*)(table + idx * D);   // 512B row
        float2* dst = (float2*)(sB + r * STRIDE);               // 8B aligned
#pragma unroll
        for (int q = 0; q < 16; ++q)
            dst[l + q * 4] = src[l + q * 4];
    }
    __syncthreads();

    // ---- S[k][m] = tanh(AM[k] . B[m]) : 64x64x128, 4x4 register tiles ----
    {
        const int tx = t & 15, ty = t >> 4;
        const float* pa = sAM + ty * STRIDE;   // rows ty+16p  (broadcast loads)
        const float* pb = sB  + tx * STRIDE;   // rows tx+16q  (conflict-free)
        float acc[4][4];
#pragma unroll
        for (int p = 0; p < 4; ++p)
#pragma unroll
            for (int q = 0; q < 4; ++q) acc[p][q] = 0.f;

#pragma unroll 2
        for (int d = 0; d < D; ++d) {
            float a[4], b[4];
#pragma unroll
            for (int p = 0; p < 4; ++p) a[p] = pa[p * 16 * STRIDE + d];
#pragma unroll
            for (int q = 0; q < 4; ++q) b[q] = pb[q * 16 * STRIDE + d];
#pragma unroll
            for (int p = 0; p < 4; ++p)
#pragma unroll
                for (int q = 0; q < 4; ++q)
                    acc[p][q] = fmaf(a[p], b[q], acc[p][q]);
        }
#pragma unroll
        for (int p = 0; p < 4; ++p)
#pragma unroll
            for (int q = 0; q < 4; ++q)
                sS[(ty + 16 * p) * SSTRIDE + tx + 16 * q] = tanhf(acc[p][q]);
    }
    __syncthreads();

    // ---- row means (over m) and col means (over k) ----
    if (t < 64) {
        float s = 0.f;
        const float* row = sS + t * SSTRIDE;
#pragma unroll 8
        for (int m = 0; m < 64; ++m) s += row[m];
        rw[t] = s * (1.f / 64.f);
    } else if (t < 128) {
        const int m = t - 64;
        float s = 0.f;
#pragma unroll 8
        for (int k2 = 0; k2 < 64; ++k2) s += sS[k2 * SSTRIDE + m];
        cw[m] = s * (1.f / 64.f);
    }
    __syncthreads();

    // ---- dual softmax over the two 64-vectors ----
    if (t < 64) red[t] = rw[t];
    else if (t < 128) red[t] = cw[t - 64];
    __syncthreads();
    for (int s = 32; s >= 1; s >>= 1) {
        if (t < s) red[t] = fmaxf(red[t], red[t + s]);
        else if (t >= 64 && t < 64 + s) red[t] = fmaxf(red[t], red[t + s]);
        __syncthreads();
    }
    const float rmax = red[0], cmax = red[64];
    __syncthreads();
    if (t < 64)      { float e = expf(rw[t] - rmax);      rw[t] = e;      red[t] = e; }
    else if (t < 128){ float e = expf(cw[t - 64] - cmax); cw[t - 64] = e; red[t] = e; }
    __syncthreads();
    for (int s = 32; s >= 1; s >>= 1) {
        if (t < s) red[t] += red[t + s];
        else if (t >= 64 && t < 64 + s) red[t] += red[t + s];
        __syncthreads();
    }
    const float rsum = red[0], csum = red[64];
    __syncthreads();

    // ---- new_A = rows @ A (A gathered from table, L2-hot), new_B = cols @ B ----
    if (t < 128) {
        float s = 0.f;
#pragma unroll 4
        for (int k2 = 0; k2 < 64; ++k2)
            s = fmaf(rw[k2], table[(size_t)sIdx[k2] * D + t], s);
        nA[t] = s / rsum;
    } else {
        const int dd = t - 128;
        float s = 0.f;
#pragma unroll 4
        for (int k2 = 0; k2 < 64; ++k2)
            s = fmaf(cw[k2], sB[k2 * STRIDE + dd], s);
        nB[dd] = s / csum;
    }
    __syncthreads();

    // ---- bilinear: con = new_A^T W new_B ----
    if (t < 128) {
        float s = 0.f;
#pragma unroll 4
        for (int d = 0; d < D; ++d)
            s = fmaf(nA[d], W[d * D + t], s);
        red[t] = s * nB[t];
    } else {
        red[t] = 0.f;
    }
    __syncthreads();
    for (int s = 128; s >= 1; s >>= 1) {
        if (t < s) red[t] += red[t + s];
        __syncthreads();
    }
    const float con = red[0] + b_bi[0];
    __syncthreads();

    // ---- string cosine branch: three 200-length reductions ----
    float p11 = 0.f, p22 = 0.f, p12 = 0.f;
    if (t < DS) {
        float x1 = str_t1[t];
        float x2 = str_t2s[c * DS + t];
        p11 = x1 * x1; p22 = x2 * x2; p12 = x1 * x2;
    }
    red[t] = p11;
    __syncthreads();
    for (int s = 128; s >= 1; s >>= 1) {
        if (t < s) red[t] += red[t + s];
        __syncthreads();
    }
    if (t == 0) sc[0] = red[0];
    __syncthreads();
    red[t] = p22;
    __syncthreads();
    for (int s = 128; s >= 1; s >>= 1) {
        if (t < s) red[t] += red[t + s];
        __syncthreads();
    }
    if (t == 0) sc[1] = red[0];
    __syncthreads();
    red[t] = p12;
    __syncthreads();
    for (int s = 128; s >= 1; s >>= 1) {
        if (t < s) red[t] += red[t + s];
        __syncthreads();
    }

    if (t == 0) {
        float n1 = fmaxf(sqrtf(sc[0]), 1e-8f);
        float n2 = fmaxf(sqrtf(sc[1]), 1e-8f);
        float str_score = red[0] / (n1 * n2);
        out[c] = 0.5f * str_score + 0.5f * con;
    }
}

static const int SMEM_BYTES =
    (K_CTX * STRIDE * 2 + K_CTX * SSTRIDE + 256 + 64 + 64 + 128 + 128 + 4) * 4;

extern "C" void kernel_launch(void* const* d_in, const int* in_sizes, int n_in,
                              void* d_out, int out_size) {
    const float* table   = (const float*)d_in[0];
    const float* str_t1  = (const float*)d_in[1];
    const float* str_t2s = (const float*)d_in[2];
    const float* att_mat = (const float*)d_in[3];
    const float* W_bi    = (const float*)d_in[4];
    const float* b_bi    = (const float*)d_in[5];
    const int*   t1_ctx  = (const int*)d_in[6];   // int32 (JAX x64 disabled)
    const int*   t2_ctx  = (const int*)d_in[7];
    float* out = (float*)d_out;

    cudaFuncSetAttribute(main_kernel,
                         cudaFuncAttributeMaxDynamicSharedMemorySize, SMEM_BYTES);

    prep_kernel<<<K_CTX, D>>>(table, att_mat, t1_ctx);
    main_kernel<<<256, 256, SMEM_BYTES>>>(table, str_t1, str_t2s, W_bi, b_bi,
                                          t1_ctx, t2_ctx, out);
}